// round 2
// baseline (speedup 1.0000x reference)
#include <cuda_runtime.h>
#include <cstdint>

// Shapes (fixed by the problem)
#define B 8
#define D 256
#define HW (128 * 128)        // 16384
#define C 80
#define NPIX (B * HW)         // 131072
#define RANGE_EXTENDER 10.0f
#define EPS 1e-8f
#define KT 128                // K-chunk staged through shared (128*80*4B = 40KB)
#define CH 40                 // channels per thread (C split across even/odd threads)

typedef unsigned long long u64;

// Pre-scaled, transposed weights: g_w[d * C + c] = w[c][d]/||w_c|| * asf[c] * 10
__device__ float g_w[D * C];

// ---------------------------------------------------------------------------
// Packed fp32x2 helpers (sm_100+; ptxas never auto-fuses these)
// ---------------------------------------------------------------------------
__device__ __forceinline__ u64 fma2(u64 a, u64 b, u64 c) {
    u64 d;
    asm("fma.rn.f32x2 %0, %1, %2, %3;" : "=l"(d) : "l"(a), "l"(b), "l"(c));
    return d;
}
__device__ __forceinline__ u64 pack2(float lo, float hi) {
    u64 d;
    asm("mov.b64 %0, {%1, %2};" : "=l"(d) : "f"(lo), "f"(hi));
    return d;
}
__device__ __forceinline__ void unpack2(u64 v, float& lo, float& hi) {
    asm("mov.b64 {%0, %1}, %2;" : "=f"(lo), "=f"(hi) : "l"(v));
}

// ---------------------------------------------------------------------------
// Kernel 1: normalize + scale weights, transpose to [D][C]
// ---------------------------------------------------------------------------
__global__ void prep_weights_kernel(const float* __restrict__ w,
                                    const float* __restrict__ asf) {
    int c = blockIdx.x;
    int d = threadIdx.x;
    float v = w[c * D + d];

    __shared__ float red[D];
    red[d] = v * v;
    __syncthreads();
    #pragma unroll
    for (int s = D / 2; s > 0; s >>= 1) {
        if (d < s) red[d] += red[d + s];
        __syncthreads();
    }
    float norm = sqrtf(red[0]);
    float scale = asf[c] * RANGE_EXTENDER / fmaxf(norm, EPS);
    g_w[d * C + c] = v * scale;
}

// ---------------------------------------------------------------------------
// Kernel 2: fused normalize-x + GEMM, packed f32x2 math.
// Each thread: 2 adjacent pixels x 40 channels.
//   even tid -> channels [0,40), odd tid -> channels [40,80)
// Accumulators packed over channel pairs (w pairs come packed from LDS.128).
// ---------------------------------------------------------------------------
__global__ __launch_bounds__(256, 2)
void coshead_main_kernel(const float* __restrict__ x, float* __restrict__ out) {
    __shared__ float ws[KT * C];   // [d_local][c], 40KB

    const int tid    = threadIdx.x;
    const int gt     = blockIdx.x * 256 + tid;
    const int pp     = gt >> 1;                 // pixel-pair index
    const int c_base = (gt & 1) * CH;           // channel half
    const int b      = pp >> 13;                // / (HW/2)
    const int hw     = (pp & (HW / 2 - 1)) * 2; // first pixel of pair

    // x pointer for this pixel pair; stride per d is HW floats
    const float2* xp2 = reinterpret_cast<const float2*>(
        x + ((size_t)b * D) * HW + hw);

    u64 acc0[CH / 2];   // pixel 0, 20 channel-pairs
    u64 acc1[CH / 2];   // pixel 1
    #pragma unroll
    for (int i = 0; i < CH / 2; i++) { acc0[i] = 0ULL; acc1[i] = 0ULL; }
    u64 norm2 = 0ULL;   // {sum x0^2, sum x1^2}

    for (int kt = 0; kt < D / KT; kt++) {
        __syncthreads();
        // cooperative weight stage: KT*C = 10240 floats, 40 per thread (float4)
        {
            const float4* src = reinterpret_cast<const float4*>(
                g_w + kt * (KT * C));
            float4* dst = reinterpret_cast<float4*>(ws);
            #pragma unroll
            for (int i = 0; i < (KT * C) / (256 * 4); i++)
                dst[tid + i * 256] = src[tid + i * 256];
        }
        __syncthreads();

        #pragma unroll 2
        for (int d = 0; d < KT; d++) {
            float2 xv = xp2[(size_t)(kt * KT + d) * (HW / 2)];
            u64 xpair;
            asm("mov.b64 %0, {%1, %2};" : "=l"(xpair) : "f"(xv.x), "f"(xv.y));
            norm2 = fma2(xpair, xpair, norm2);
            u64 xa = pack2(xv.x, xv.x);
            u64 xb = pack2(xv.y, xv.y);

            const ulonglong2* wrow = reinterpret_cast<const ulonglong2*>(
                &ws[d * C + c_base]);
            #pragma unroll
            for (int i = 0; i < CH / 4; i++) {       // 10 x LDS.128
                ulonglong2 w2 = wrow[i];             // 2 packed channel-pairs
                acc0[2 * i + 0] = fma2(xa, w2.x, acc0[2 * i + 0]);
                acc1[2 * i + 0] = fma2(xb, w2.x, acc1[2 * i + 0]);
                acc0[2 * i + 1] = fma2(xa, w2.y, acc0[2 * i + 1]);
                acc1[2 * i + 1] = fma2(xb, w2.y, acc1[2 * i + 1]);
            }
        }
    }

    float n0, n1;
    unpack2(norm2, n0, n1);
    const float inv0 = 1.0f / fmaxf(sqrtf(n0), EPS);
    const float inv1 = 1.0f / fmaxf(sqrtf(n1), EPS);

    // out[b][c][hw], pixels hw and hw+1 adjacent -> float2 store per channel
    float* ob = out + ((size_t)b * C + c_base) * HW + hw;
    #pragma unroll
    for (int i = 0; i < CH / 2; i++) {
        float a0lo, a0hi, a1lo, a1hi;
        unpack2(acc0[i], a0lo, a0hi);
        unpack2(acc1[i], a1lo, a1hi);
        float2 v0 = make_float2(a0lo * inv0, a1lo * inv1);  // channel 2i
        float2 v1 = make_float2(a0hi * inv0, a1hi * inv1);  // channel 2i+1
        *reinterpret_cast<float2*>(ob + (size_t)(2 * i) * HW)     = v0;
        *reinterpret_cast<float2*>(ob + (size_t)(2 * i + 1) * HW) = v1;
    }
}

// ---------------------------------------------------------------------------
// Launch
// ---------------------------------------------------------------------------
extern "C" void kernel_launch(void* const* d_in, const int* in_sizes, int n_in,
                              void* d_out, int out_size) {
    const float* x   = (const float*)d_in[0];  // [B, D, H, W]
    const float* w   = (const float*)d_in[1];  // [C, D]
    const float* asf = (const float*)d_in[2];  // [C]
    float* out = (float*)d_out;                // [B, C, H, W]

    prep_weights_kernel<<<C, D>>>(w, asf);
    coshead_main_kernel<<<NPIX / 256, 256>>>(x, out);
}

// round 3
// speedup vs baseline: 2.1263x; 2.1263x over previous
#include <cuda_runtime.h>
#include <cstdint>

// Shapes (fixed by the problem)
#define B 8
#define D 256
#define HW (128 * 128)        // 16384
#define C 80
#define NPIX (B * HW)         // 131072
#define RANGE_EXTENDER 10.0f
#define EPS 1e-8f

#define KT 32                 // K-chunk staged through shared
#define PXT 128               // pixels per block tile
#define NTHREADS 320          // 32 px-cols x 10 ch-rows
// thread tile: 4 px x 8 ch -> 16 u64 f32x2 accumulators

typedef unsigned long long u64;

// Pre-scaled, transposed weights: g_w[d * C + c] = w[c][d]/||w_c|| * asf[c] * 10
__device__ float g_w[D * C];

// ---------------------------------------------------------------------------
// Packed fp32x2 helpers (sm_100+; ptxas never auto-fuses these)
// ---------------------------------------------------------------------------
__device__ __forceinline__ u64 fma2(u64 a, u64 b, u64 c) {
    u64 d;
    asm("fma.rn.f32x2 %0, %1, %2, %3;" : "=l"(d) : "l"(a), "l"(b), "l"(c));
    return d;
}
__device__ __forceinline__ u64 pack2(float lo, float hi) {
    u64 d;
    asm("mov.b64 %0, {%1, %2};" : "=l"(d) : "f"(lo), "f"(hi));
    return d;
}
__device__ __forceinline__ void unpack2(u64 v, float& lo, float& hi) {
    asm("mov.b64 {%0, %1}, %2;" : "=f"(lo), "=f"(hi) : "l"(v));
}

// ---------------------------------------------------------------------------
// Kernel 1: normalize + scale weights, transpose to [D][C]
// ---------------------------------------------------------------------------
__global__ void prep_weights_kernel(const float* __restrict__ w,
                                    const float* __restrict__ asf) {
    int c = blockIdx.x;
    int d = threadIdx.x;
    float v = w[c * D + d];

    __shared__ float red[D];
    red[d] = v * v;
    __syncthreads();
    #pragma unroll
    for (int s = D / 2; s > 0; s >>= 1) {
        if (d < s) red[d] += red[d + s];
        __syncthreads();
    }
    float norm = sqrtf(red[0]);
    float scale = asf[c] * RANGE_EXTENDER / fmaxf(norm, EPS);
    g_w[d * C + c] = v * scale;
}

// ---------------------------------------------------------------------------
// Kernel 2: 2D-register-tiled fused normalize-x + GEMM, packed f32x2 math.
// Block tile: 128 pixels x 80 channels, K staged in chunks of 32.
// Thread (px_col, ch_row): 4 contiguous pixels x 8 channels (4 ch-pairs).
// ch_row is warp-uniform -> weight LDS are broadcasts.
// ---------------------------------------------------------------------------
__global__ __launch_bounds__(NTHREADS, 2)
void coshead_main_kernel(const float* __restrict__ x, float* __restrict__ out) {
    __shared__ float xs[KT * PXT];    // [k][px]   16 KB
    __shared__ float ws[KT * C];      // [k][c]    10 KB
    __shared__ float norms[PXT];      // inv-norm per pixel

    const int tid    = threadIdx.x;
    const int px_col = tid & 31;        // 0..31
    const int ch_row = tid >> 5;        // 0..9
    const int px0    = px_col * 4;      // first of 4 pixels in tile
    const int c0     = ch_row * 8;      // first of 8 channels

    const int tile    = blockIdx.x;
    const int b       = (tile * PXT) >> 14;       // / HW
    const int hw_base = (tile * PXT) & (HW - 1);

    const float* xg = x + ((size_t)b * D) * HW + hw_base;

    // acc[px][cp]: f32x2 over channel pair {c0+2cp, c0+2cp+1}
    u64 acc[4][4];
    #pragma unroll
    for (int p = 0; p < 4; p++)
        #pragma unroll
        for (int q = 0; q < 4; q++) acc[p][q] = 0ULL;

    float n2[4] = {0.f, 0.f, 0.f, 0.f};   // used by ch_row 0 only

    for (int kt = 0; kt < D / KT; kt++) {
        __syncthreads();
        // stage x tile: KT rows x 128 px, each row contiguous in gmem
        {
            const float4* gx = reinterpret_cast<const float4*>(
                xg + (size_t)(kt * KT) * HW);
            float4* sx = reinterpret_cast<float4*>(xs);
            for (int i = tid; i < KT * (PXT / 4); i += NTHREADS) {
                int row = i >> 5;          // /32 float4 per row
                int col = i & 31;
                sx[i] = gx[(size_t)row * (HW / 4) + col];
            }
        }
        // stage w tile: KT*C floats, contiguous in g_w
        {
            const float4* gw = reinterpret_cast<const float4*>(
                g_w + kt * (KT * C));
            float4* sw = reinterpret_cast<float4*>(ws);
            for (int i = tid; i < KT * (C / 4); i += NTHREADS)
                sw[i] = gw[i];
        }
        __syncthreads();

        #pragma unroll 8
        for (int k = 0; k < KT; k++) {
            float4 xv = *reinterpret_cast<const float4*>(&xs[k * PXT + px0]);
            if (ch_row == 0) {
                n2[0] = fmaf(xv.x, xv.x, n2[0]);
                n2[1] = fmaf(xv.y, xv.y, n2[1]);
                n2[2] = fmaf(xv.z, xv.z, n2[2]);
                n2[3] = fmaf(xv.w, xv.w, n2[3]);
            }
            u64 xp0 = pack2(xv.x, xv.x);
            u64 xp1 = pack2(xv.y, xv.y);
            u64 xp2 = pack2(xv.z, xv.z);
            u64 xp3 = pack2(xv.w, xv.w);

            const ulonglong2* wrow = reinterpret_cast<const ulonglong2*>(
                &ws[k * C + c0]);
            ulonglong2 wa = wrow[0];   // ch pairs 0,1
            ulonglong2 wb = wrow[1];   // ch pairs 2,3

            acc[0][0] = fma2(xp0, wa.x, acc[0][0]);
            acc[1][0] = fma2(xp1, wa.x, acc[1][0]);
            acc[2][0] = fma2(xp2, wa.x, acc[2][0]);
            acc[3][0] = fma2(xp3, wa.x, acc[3][0]);
            acc[0][1] = fma2(xp0, wa.y, acc[0][1]);
            acc[1][1] = fma2(xp1, wa.y, acc[1][1]);
            acc[2][1] = fma2(xp2, wa.y, acc[2][1]);
            acc[3][1] = fma2(xp3, wa.y, acc[3][1]);
            acc[0][2] = fma2(xp0, wb.x, acc[0][2]);
            acc[1][2] = fma2(xp1, wb.x, acc[1][2]);
            acc[2][2] = fma2(xp2, wb.x, acc[2][2]);
            acc[3][2] = fma2(xp3, wb.x, acc[3][2]);
            acc[0][3] = fma2(xp0, wb.y, acc[0][3]);
            acc[1][3] = fma2(xp1, wb.y, acc[1][3]);
            acc[2][3] = fma2(xp2, wb.y, acc[2][3]);
            acc[3][3] = fma2(xp3, wb.y, acc[3][3]);
        }
    }

    // share inverse norms
    if (ch_row == 0) {
        #pragma unroll
        for (int p = 0; p < 4; p++)
            norms[px0 + p] = 1.0f / fmaxf(sqrtf(n2[p]), EPS);
    }
    __syncthreads();
    float inv[4];
    #pragma unroll
    for (int p = 0; p < 4; p++) inv[p] = norms[px0 + p];

    // write out[b][c][hw]: per channel, 4 contiguous pixels -> STG.128
    float* ob = out + ((size_t)b * C + c0) * HW + hw_base + px0;
    #pragma unroll
    for (int q = 0; q < 4; q++) {           // channel pair q: c0+2q, c0+2q+1
        float lo0, hi0, lo1, hi1, lo2, hi2, lo3, hi3;
        unpack2(acc[0][q], lo0, hi0);
        unpack2(acc[1][q], lo1, hi1);
        unpack2(acc[2][q], lo2, hi2);
        unpack2(acc[3][q], lo3, hi3);
        float4 ve = make_float4(lo0 * inv[0], lo1 * inv[1],
                                lo2 * inv[2], lo3 * inv[3]);
        float4 vo = make_float4(hi0 * inv[0], hi1 * inv[1],
                                hi2 * inv[2], hi3 * inv[3]);
        *reinterpret_cast<float4*>(ob + (size_t)(2 * q) * HW)     = ve;
        *reinterpret_cast<float4*>(ob + (size_t)(2 * q + 1) * HW) = vo;
    }
}

// ---------------------------------------------------------------------------
// Launch
// ---------------------------------------------------------------------------
extern "C" void kernel_launch(void* const* d_in, const int* in_sizes, int n_in,
                              void* d_out, int out_size) {
    const float* x   = (const float*)d_in[0];  // [B, D, H, W]
    const float* w   = (const float*)d_in[1];  // [C, D]
    const float* asf = (const float*)d_in[2];  // [C]
    float* out = (float*)d_out;                // [B, C, H, W]

    prep_weights_kernel<<<C, D>>>(w, asf);
    coshead_main_kernel<<<NPIX / PXT, NTHREADS>>>(x, out);
}

// round 4
// speedup vs baseline: 2.2684x; 1.0668x over previous
#include <cuda_runtime.h>
#include <cstdint>

// Shapes (fixed by the problem)
#define B 8
#define D 256
#define HW (128 * 128)        // 16384
#define C 80
#define NPIX (B * HW)         // 131072
#define RANGE_EXTENDER 10.0f
#define EPS 1e-8f

#define KT 16                 // K-chunk per pipeline stage
#define NTILES (D / KT)       // 16
#define PXT 128               // pixels per block tile
#define NTHREADS 320          // 32 px-cols x 10 ch-rows

typedef unsigned long long u64;

// Pre-scaled, transposed weights: g_w[d * C + c] = w[c][d]/||w_c|| * asf[c] * 10
__device__ float g_w[D * C];

// ---------------------------------------------------------------------------
// Packed fp32x2 helpers (sm_100+; ptxas never auto-fuses these)
// ---------------------------------------------------------------------------
__device__ __forceinline__ u64 fma2(u64 a, u64 b, u64 c) {
    u64 d;
    asm("fma.rn.f32x2 %0, %1, %2, %3;" : "=l"(d) : "l"(a), "l"(b), "l"(c));
    return d;
}
__device__ __forceinline__ u64 pack2(float lo, float hi) {
    u64 d;
    asm("mov.b64 %0, {%1, %2};" : "=l"(d) : "f"(lo), "f"(hi));
    return d;
}
__device__ __forceinline__ void unpack2(u64 v, float& lo, float& hi) {
    asm("mov.b64 {%0, %1}, %2;" : "=f"(lo), "=f"(hi) : "l"(v));
}

__device__ __forceinline__ void cp_async16(void* smem_dst, const void* gmem_src) {
    uint32_t s = (uint32_t)__cvta_generic_to_shared(smem_dst);
    asm volatile("cp.async.cg.shared.global [%0], [%1], 16;"
                 :: "r"(s), "l"(gmem_src) : "memory");
}
__device__ __forceinline__ void cp_commit() {
    asm volatile("cp.async.commit_group;" ::: "memory");
}
template <int N>
__device__ __forceinline__ void cp_wait() {
    asm volatile("cp.async.wait_group %0;" :: "n"(N) : "memory");
}

// ---------------------------------------------------------------------------
// Kernel 1: normalize + scale weights, transpose to [D][C]
// ---------------------------------------------------------------------------
__global__ void prep_weights_kernel(const float* __restrict__ w,
                                    const float* __restrict__ asf) {
    int c = blockIdx.x;
    int d = threadIdx.x;
    float v = w[c * D + d];

    __shared__ float red[D];
    red[d] = v * v;
    __syncthreads();
    #pragma unroll
    for (int s = D / 2; s > 0; s >>= 1) {
        if (d < s) red[d] += red[d + s];
        __syncthreads();
    }
    float norm = sqrtf(red[0]);
    float scale = asf[c] * RANGE_EXTENDER / fmaxf(norm, EPS);
    g_w[d * C + c] = v * scale;
}

// ---------------------------------------------------------------------------
// Kernel 2: f32x2 register-tiled GEMM with cp.async double-buffered x staging.
// Block tile: 128 pixels x 80 channels. Thread: 4 px x 8 ch (16 fma2/k).
// Weights read via warp-uniform LDG (L1-resident, 80KB total).
// ---------------------------------------------------------------------------
__global__ __launch_bounds__(NTHREADS, 2)
void coshead_main_kernel(const float* __restrict__ x, float* __restrict__ out) {
    __shared__ float xs[2][KT * PXT];   // 2 x 8KB
    __shared__ float norms[PXT];

    const int tid    = threadIdx.x;
    const int px_col = tid & 31;        // 0..31
    const int ch_row = tid >> 5;        // 0..9  (warp id)
    const int px0    = px_col * 4;
    const int c0     = ch_row * 8;

    const int tile    = blockIdx.x;
    const int b       = (tile * PXT) >> 14;
    const int hw_base = (tile * PXT) & (HW - 1);

    // x as float4 rows: row k has HW/4 float4s; our tile starts at hw_base/4
    const float4* gx = reinterpret_cast<const float4*>(
        x + ((size_t)b * D) * HW + hw_base);

    // stage tile t (k rows [t*KT, t*KT+KT)) into buffer bufsel
    auto stage = [&](int t, int bufsel) {
        // KT*PXT/4 = 512 float4s, 320 threads
        #pragma unroll
        for (int i = tid; i < KT * (PXT / 4); i += NTHREADS) {
            int row = i >> 5;          // /32 float4 per 128-px row
            int col = i & 31;
            cp_async16(&xs[bufsel][row * PXT + col * 4],
                       &gx[(size_t)(t * KT + row) * (HW / 4) + col]);
        }
        cp_commit();
    };

    u64 acc[4][4];
    #pragma unroll
    for (int p = 0; p < 4; p++)
        #pragma unroll
        for (int q = 0; q < 4; q++) acc[p][q] = 0ULL;
    float n2[4] = {0.f, 0.f, 0.f, 0.f};

    stage(0, 0);
    stage(1, 1);

    for (int t = 0; t < NTILES; t++) {
        const int buf = t & 1;
        if (t + 2 < NTILES) cp_wait<1>(); else cp_wait<0>();
        __syncthreads();

        const float* wbase = g_w + (size_t)(t * KT) * C + c0;

        #pragma unroll
        for (int k = 0; k < KT; k++) {
            float4 xv = *reinterpret_cast<const float4*>(&xs[buf][k * PXT + px0]);
            // warp-uniform weight loads (L1 hit after warmup)
            const float4* wrow = reinterpret_cast<const float4*>(wbase + (size_t)k * C);
            float4 w0 = __ldg(wrow);
            float4 w1 = __ldg(wrow + 1);

            if (ch_row == 0) {
                n2[0] = fmaf(xv.x, xv.x, n2[0]);
                n2[1] = fmaf(xv.y, xv.y, n2[1]);
                n2[2] = fmaf(xv.z, xv.z, n2[2]);
                n2[3] = fmaf(xv.w, xv.w, n2[3]);
            }
            u64 xp0 = pack2(xv.x, xv.x);
            u64 xp1 = pack2(xv.y, xv.y);
            u64 xp2 = pack2(xv.z, xv.z);
            u64 xp3 = pack2(xv.w, xv.w);
            u64 wa = pack2(w0.x, w0.y);   // ch pair 0
            u64 wb = pack2(w0.z, w0.w);   // ch pair 1
            u64 wc = pack2(w1.x, w1.y);   // ch pair 2
            u64 wd = pack2(w1.z, w1.w);   // ch pair 3

            acc[0][0] = fma2(xp0, wa, acc[0][0]);
            acc[1][0] = fma2(xp1, wa, acc[1][0]);
            acc[2][0] = fma2(xp2, wa, acc[2][0]);
            acc[3][0] = fma2(xp3, wa, acc[3][0]);
            acc[0][1] = fma2(xp0, wb, acc[0][1]);
            acc[1][1] = fma2(xp1, wb, acc[1][1]);
            acc[2][1] = fma2(xp2, wb, acc[2][1]);
            acc[3][1] = fma2(xp3, wb, acc[3][1]);
            acc[0][2] = fma2(xp0, wc, acc[0][2]);
            acc[1][2] = fma2(xp1, wc, acc[1][2]);
            acc[2][2] = fma2(xp2, wc, acc[2][2]);
            acc[3][2] = fma2(xp3, wc, acc[3][2]);
            acc[0][3] = fma2(xp0, wd, acc[0][3]);
            acc[1][3] = fma2(xp1, wd, acc[1][3]);
            acc[2][3] = fma2(xp2, wd, acc[2][3]);
            acc[3][3] = fma2(xp3, wd, acc[3][3]);
        }

        __syncthreads();                       // all warps done reading xs[buf]
        if (t + 2 < NTILES) stage(t + 2, buf); // refill the freed buffer
    }

    // share inverse norms
    if (ch_row == 0) {
        #pragma unroll
        for (int p = 0; p < 4; p++)
            norms[px0 + p] = 1.0f / fmaxf(sqrtf(n2[p]), EPS);
    }
    __syncthreads();
    float inv[4];
    #pragma unroll
    for (int p = 0; p < 4; p++) inv[p] = norms[px0 + p];

    // write out[b][c][hw]: per channel, 4 contiguous pixels -> STG.128
    float* ob = out + ((size_t)b * C + c0) * HW + hw_base + px0;
    #pragma unroll
    for (int q = 0; q < 4; q++) {
        float lo0, hi0, lo1, hi1, lo2, hi2, lo3, hi3;
        unpack2(acc[0][q], lo0, hi0);
        unpack2(acc[1][q], lo1, hi1);
        unpack2(acc[2][q], lo2, hi2);
        unpack2(acc[3][q], lo3, hi3);
        float4 ve = make_float4(lo0 * inv[0], lo1 * inv[1],
                                lo2 * inv[2], lo3 * inv[3]);
        float4 vo = make_float4(hi0 * inv[0], hi1 * inv[1],
                                hi2 * inv[2], hi3 * inv[3]);
        *reinterpret_cast<float4*>(ob + (size_t)(2 * q) * HW)     = ve;
        *reinterpret_cast<float4*>(ob + (size_t)(2 * q + 1) * HW) = vo;
    }
}

// ---------------------------------------------------------------------------
// Launch
// ---------------------------------------------------------------------------
extern "C" void kernel_launch(void* const* d_in, const int* in_sizes, int n_in,
                              void* d_out, int out_size) {
    const float* x   = (const float*)d_in[0];  // [B, D, H, W]
    const float* w   = (const float*)d_in[1];  // [C, D]
    const float* asf = (const float*)d_in[2];  // [C]
    float* out = (float*)d_out;                // [B, C, H, W]

    prep_weights_kernel<<<C, D>>>(w, asf);
    coshead_main_kernel<<<NPIX / PXT, NTHREADS>>>(x, out);
}